// round 16
// baseline (speedup 1.0000x reference)
#include <cuda_runtime.h>
#include <cstdint>

// Top-64 per row with ReLU, zeros elsewhere. One CTA per row, SINGLE fused
// data pass with the ENTIRE per-thread row share (12x LDG.128) front-batched
// before the 12x STG.128 zero-stores. __launch_bounds__(512,2) gives a 64-reg
// budget so all 12 loads are simultaneously in flight (true MLP=12);
// occupancy 50% is deliberately spent on flight depth — confirmed cheap in
// R13/R14 (issue ~27%, warps park on long-scoreboard regardless).
// TCAND=2.6 -> ~114 candidates/row. Fast path: all-pairs rank epilogue
// (jax.lax.top_k tie semantics, lowest index wins). Radix select for nc>512;
// generic fallbacks keep correctness for any input distribution.

constexpr int NCOLS    = 24576;
constexpr int NT       = 512;              // 16 warps
constexpr int NW       = NT / 32;
constexpr int KSEL     = 64;
constexpr int VEC_IT   = NCOLS / (NT * 4); // 12 float4 per thread
constexpr int BATCH    = 12;               // whole row share in one batch
constexpr int CAND_MAX = 2048;
constexpr int MAX_EQ   = 128;
constexpr float TCAND  = 2.6f;

constexpr int SMEM_WORDS = 256 + 32 + 4 + 4 + NW + CAND_MAX + CAND_MAX + MAX_EQ;
constexpr int SMEM_BYTES = SMEM_WORDS * 4;

__device__ __forceinline__ uint32_t key_of(uint32_t b) {
    uint32_t mask = (uint32_t)((int32_t)b >> 31) | 0x80000000u;
    return b ^ mask;  // larger float <=> larger unsigned key
}
__device__ __forceinline__ float relu_of_key(uint32_t k) {
    return (k & 0x80000000u) ? __uint_as_float(k ^ 0x80000000u) : 0.0f;
}

__device__ __forceinline__ void collect4(
    const float4& v, int base, uint32_t* cnt, uint32_t* ck, uint32_t* ci)
{
    if (v.x > TCAND) { uint32_t p = atomicAdd(&cnt[0], 1u);
        if (p < CAND_MAX) { ck[p] = __float_as_uint(v.x) | 0x80000000u; ci[p] = base; } }
    if (v.y > TCAND) { uint32_t p = atomicAdd(&cnt[0], 1u);
        if (p < CAND_MAX) { ck[p] = __float_as_uint(v.y) | 0x80000000u; ci[p] = base + 1; } }
    if (v.z > TCAND) { uint32_t p = atomicAdd(&cnt[0], 1u);
        if (p < CAND_MAX) { ck[p] = __float_as_uint(v.z) | 0x80000000u; ci[p] = base + 2; } }
    if (v.w > TCAND) { uint32_t p = atomicAdd(&cnt[0], 1u);
        if (p < CAND_MAX) { ck[p] = __float_as_uint(v.w) | 0x80000000u; ci[p] = base + 3; } }
}

// suffix-select over nbins (<=256): thread t holds count v of bin t. Finds bin
// where suffix count crosses rank Kre. Writes sel={bin, strictly_above, count}.
__device__ __forceinline__ void suffix_select(
    uint32_t v, uint32_t* scanb, uint32_t* sel,
    int nbins, uint32_t Kre, int t, int lane, int wid)
{
    uint32_t s = v;  // inclusive suffix within warp
    #pragma unroll
    for (int off = 1; off < 32; off <<= 1) {
        uint32_t u = __shfl_down_sync(0xFFFFFFFFu, s, off);
        if (lane + off < 32) s += u;
    }
    const int nw = (nbins + 31) >> 5;
    if (lane == 0 && wid < nw) scanb[wid] = s;
    __syncthreads();
    if (t < 32) {
        uint32_t w = (t < nw) ? scanb[t] : 0u;
        uint32_t ws = w;
        #pragma unroll
        for (int off = 1; off < 32; off <<= 1) {
            uint32_t u = __shfl_down_sync(0xFFFFFFFFu, ws, off);
            if (t + off < 32) ws += u;
        }
        if (t < nw) scanb[t] = ws - w;   // exclusive suffix over warps above
    }
    __syncthreads();
    if (t < nbins) {
        uint32_t above = (s - v) + scanb[wid];
        if (above < Kre && above + v >= Kre) {
            sel[0] = (uint32_t)t; sel[1] = above; sel[2] = v;
        }
    }
    __syncthreads();
}

__global__ __launch_bounds__(NT, 2)
void topk_relu_kernel(const float* __restrict__ x, float* __restrict__ out) {
    extern __shared__ uint32_t smem[];
    uint32_t* hist  = smem;              // [256]
    uint32_t* scanb = hist + 256;        // [32]
    uint32_t* sel   = scanb + 32;        // [4]
    uint32_t* cnt   = sel + 4;           // [0]=cand, [1]=eq, [2]=npos
    uint32_t* wred  = cnt + 4;           // [NW]
    uint32_t* ck    = wred + NW;         // [CAND_MAX] candidate keys
    uint32_t* ci    = ck + CAND_MAX;     // [CAND_MAX] candidate indices
    uint32_t* eqi   = ci + CAND_MAX;     // [MAX_EQ]

    const int row  = blockIdx.x;
    const int t    = threadIdx.x;
    const int lane = t & 31;
    const int wid  = t >> 5;
    const float4* __restrict__ xv =
        reinterpret_cast<const float4*>(x + (size_t)row * NCOLS);
    float* __restrict__ orow = out + (size_t)row * NCOLS;
    float4* __restrict__ ov = reinterpret_cast<float4*>(orow);

    if (t == 0) { cnt[0] = 0; cnt[1] = 0; }
    __syncthreads();

    // ---- fused main pass: 12 front-batched loads, 12 zero-stores, collect ----
    const float4 z4 = make_float4(0.f, 0.f, 0.f, 0.f);
    {
        const float4* xp = xv + t;   // stride NT, constant offsets below
        float4* op = ov + t;
        float4 v[BATCH];
        #pragma unroll
        for (int b = 0; b < BATCH; b++)
            v[b] = __ldcs(xp + b * NT);
        #pragma unroll
        for (int b = 0; b < BATCH; b++)
            __stcs(op + b * NT, z4);
        #pragma unroll
        for (int b = 0; b < BATCH; b++) {
            float m = fmaxf(fmaxf(v[b].x, v[b].y), fmaxf(v[b].z, v[b].w));
            if (m > TCAND) collect4(v[b], (b * NT + t) * 4, cnt, ck, ci);
        }
    }
    __syncthreads();

    const uint32_t ncand = cnt[0];

    // ---- fast path A: rank epilogue (one thread per candidate) ----
    if (ncand >= KSEL && ncand <= (uint32_t)NT) {
        if (t < (int)ncand) {
            uint32_t myk = ck[t], myi = ci[t];
            uint32_t r = 0;
            for (uint32_t j = 0; j < ncand; j++) {
                uint32_t kj = ck[j];
                uint32_t ij = ci[j];
                r += (kj > myk) || (kj == myk && ij < myi);
            }
            if (r < KSEL) orow[myi] = relu_of_key(myk);
        }
        return;
    }

    uint32_t Pc, Rr, nc;
    int shc;
    if (ncand > (uint32_t)NT && ncand <= CAND_MAX) {
        // ---- fast path B: larger candidate set -> radix select ----
        Pc = 0; shc = 32; Rr = KSEL; nc = ncand;
    } else {
        // ---- rare paths: need the positive count (L2-resident re-read) ----
        uint32_t c0 = 0;
        #pragma unroll 4
        for (int it = 0; it < VEC_IT; it++) {
            float4 v = __ldcs(xv + it * NT + t);
            c0 += (v.x > 0.0f) + (v.y > 0.0f) + (v.z > 0.0f) + (v.w > 0.0f);
        }
        #pragma unroll
        for (int off = 16; off > 0; off >>= 1)
            c0 += __shfl_down_sync(0xFFFFFFFFu, c0, off);
        if (lane == 0) wred[wid] = c0;
        __syncthreads();
        if (t == 0) {
            uint32_t s = 0;
            #pragma unroll
            for (int w = 0; w < NW; w++) s += wred[w];
            cnt[2] = s;
        }
        __syncthreads();
        const uint32_t npos = cnt[2];

        if (npos < KSEL) {
            // 64th largest <= 0: output is exactly relu(x)
            #pragma unroll 4
            for (int it = 0; it < VEC_IT; it++) {
                int vi = it * NT + t;
                float4 v = __ldcs(xv + vi);
                v.x = fmaxf(v.x, 0.0f); v.y = fmaxf(v.y, 0.0f);
                v.z = fmaxf(v.z, 0.0f); v.w = fmaxf(v.w, 0.0f);
                __stcs(ov + vi, v);
            }
            return;
        }

        // generic fallback: key-space radix refine (any distribution)
        const uint32_t* xb = reinterpret_cast<const uint32_t*>(x) + (size_t)row * NCOLS;
        uint32_t P = 0, R = KSEL, bc = NCOLS;
        int sh = 32;
        while (bc > CAND_MAX && sh > 0) {
            int nsh = (sh >= 8) ? sh - 8 : 0;
            int nb  = 1 << (sh - nsh);
            for (int i = t; i < nb; i += NT) hist[i] = 0;
            __syncthreads();
            for (int i = t; i < NCOLS; i += NT) {
                uint32_t k = key_of(xb[i]);
                if (sh == 32 || (k >> sh) == P)
                    atomicAdd(&hist[(k >> nsh) & (nb - 1)], 1u);
            }
            __syncthreads();
            uint32_t hv = (t < nb) ? hist[t] : 0u;
            suffix_select(hv, scanb, sel, nb, R, t, lane, wid);
            P  = ((sh == 32) ? 0u : (P << (sh - nsh))) | sel[0];
            R -= sel[1];
            bc = sel[2];
            sh = nsh;
            __syncthreads();
        }
        const uint32_t kLo = (sh == 32) ? 0u : (P << sh);
        const uint32_t kHi = (sh == 32) ? 0xFFFFFFFFu
                             : (uint32_t)(((((uint64_t)P) + 1ull) << sh) - 1ull);
        if (t == 0) cnt[0] = 0;
        __syncthreads();
        for (int i = t; i < NCOLS; i += NT) {
            uint32_t k = key_of(xb[i]);
            if (k > kHi) {
                orow[i] = relu_of_key(k);       // definitely top-64
            } else if (k >= kLo) {
                uint32_t p = atomicAdd(&cnt[0], 1u);
                if (p < CAND_MAX) { ck[p] = k; ci[p] = (uint32_t)i; }
            }
        }
        __syncthreads();
        nc = cnt[0]; if (nc > CAND_MAX) nc = CAND_MAX;
        Pc = P; shc = sh; Rr = R;
    }

    // ---- exact threshold: 8-bit radix select over candidates ----
    while (shc > 0) {
        int nsh = (shc >= 8) ? shc - 8 : 0;
        int nb  = 1 << (shc - nsh);
        for (int i = t; i < nb; i += NT) hist[i] = 0;
        __syncthreads();
        for (uint32_t i = t; i < nc; i += NT) {
            uint32_t k = ck[i];
            if (shc == 32 || (k >> shc) == Pc)
                atomicAdd(&hist[(k >> nsh) & (nb - 1)], 1u);
        }
        __syncthreads();
        uint32_t hv = (t < nb) ? hist[t] : 0u;
        suffix_select(hv, scanb, sel, nb, Rr, t, lane, wid);
        Pc  = ((shc == 32) ? 0u : (Pc << (shc - nsh))) | sel[0];
        Rr -= sel[1];
        shc = nsh;
        __syncthreads();
    }
    const uint32_t Tkey   = Pc;
    const uint32_t keepEq = Rr;                 // # threshold-equal keys to keep
    const float    tval   = relu_of_key(Tkey);

    // ---- scatter strictly-above candidates; collect exact ties ----
    for (uint32_t i = t; i < nc; i += NT) {
        uint32_t k = ck[i];
        if (k > Tkey) {
            orow[ci[i]] = relu_of_key(k);
        } else if (k == Tkey) {
            uint32_t p = atomicAdd(&cnt[1], 1u);
            if (p < MAX_EQ) eqi[p] = ci[i];
        }
    }
    __syncthreads();

    // ---- ties: keep the keepEq equal-keys with smallest indices ----
    uint32_t ne = cnt[1];
    if (ne > MAX_EQ) ne = MAX_EQ;
    if (ne <= keepEq) {
        for (uint32_t e = t; e < ne; e += NT) orow[eqi[e]] = tval;
    } else {
        for (uint32_t e = t; e < ne; e += NT) {
            uint32_t idx = eqi[e];
            uint32_t c = 0;
            for (uint32_t j = 0; j < ne; j++) c += (eqi[j] < idx);
            if (c < keepEq) orow[idx] = tval;
        }
    }
}

extern "C" void kernel_launch(void* const* d_in, const int* in_sizes, int n_in,
                              void* d_out, int out_size) {
    const float* x = (const float*)d_in[0];
    float* out = (float*)d_out;
    const int rows = in_sizes[0] / NCOLS;

    cudaFuncSetAttribute(topk_relu_kernel,
                         cudaFuncAttributeMaxDynamicSharedMemorySize, SMEM_BYTES);
    topk_relu_kernel<<<rows, NT, SMEM_BYTES>>>(x, out);
}

// round 17
// speedup vs baseline: 1.0463x; 1.0463x over previous
#include <cuda_runtime.h>
#include <cstdint>

// Top-64 per row with ReLU, zeros elsewhere. One CTA per row, SINGLE fused
// data pass. CONVERGED CONFIG (depth axis mapped R12-R16): 6-deep
// front-batched loads at 3 CTAs/SM (regs ~40) — deeper (12 @ 2 CTAs/SM)
// regresses on LDG-queue/wave-balance, shallower (4 @ 4 CTAs/SM) clips MLP
// at the register ceiling. Constant-offset addressing folds batch offsets
// into LDG/STG immediates.
// TCAND=2.6 -> ~114 candidates/row. Fast path: all-pairs rank epilogue
// (jax.lax.top_k tie semantics, lowest index wins). Radix select for nc>512;
// generic fallbacks keep correctness for any input distribution.

constexpr int NCOLS    = 24576;
constexpr int NT       = 512;              // 16 warps
constexpr int NW       = NT / 32;
constexpr int KSEL     = 64;
constexpr int VEC_IT   = NCOLS / (NT * 4); // 12 float4 per thread
constexpr int BATCH    = 6;                // optimum depth (R14)
constexpr int CAND_MAX = 2048;
constexpr int MAX_EQ   = 128;
constexpr float TCAND  = 2.6f;

constexpr int SMEM_WORDS = 256 + 32 + 4 + 4 + NW + CAND_MAX + CAND_MAX + MAX_EQ;
constexpr int SMEM_BYTES = SMEM_WORDS * 4;

__device__ __forceinline__ uint32_t key_of(uint32_t b) {
    uint32_t mask = (uint32_t)((int32_t)b >> 31) | 0x80000000u;
    return b ^ mask;  // larger float <=> larger unsigned key
}
__device__ __forceinline__ float relu_of_key(uint32_t k) {
    return (k & 0x80000000u) ? __uint_as_float(k ^ 0x80000000u) : 0.0f;
}

__device__ __forceinline__ void collect4(
    const float4& v, int base, uint32_t* cnt, uint32_t* ck, uint32_t* ci)
{
    if (v.x > TCAND) { uint32_t p = atomicAdd(&cnt[0], 1u);
        if (p < CAND_MAX) { ck[p] = __float_as_uint(v.x) | 0x80000000u; ci[p] = base; } }
    if (v.y > TCAND) { uint32_t p = atomicAdd(&cnt[0], 1u);
        if (p < CAND_MAX) { ck[p] = __float_as_uint(v.y) | 0x80000000u; ci[p] = base + 1; } }
    if (v.z > TCAND) { uint32_t p = atomicAdd(&cnt[0], 1u);
        if (p < CAND_MAX) { ck[p] = __float_as_uint(v.z) | 0x80000000u; ci[p] = base + 2; } }
    if (v.w > TCAND) { uint32_t p = atomicAdd(&cnt[0], 1u);
        if (p < CAND_MAX) { ck[p] = __float_as_uint(v.w) | 0x80000000u; ci[p] = base + 3; } }
}

// suffix-select over nbins (<=256): thread t holds count v of bin t. Finds bin
// where suffix count crosses rank Kre. Writes sel={bin, strictly_above, count}.
__device__ __forceinline__ void suffix_select(
    uint32_t v, uint32_t* scanb, uint32_t* sel,
    int nbins, uint32_t Kre, int t, int lane, int wid)
{
    uint32_t s = v;  // inclusive suffix within warp
    #pragma unroll
    for (int off = 1; off < 32; off <<= 1) {
        uint32_t u = __shfl_down_sync(0xFFFFFFFFu, s, off);
        if (lane + off < 32) s += u;
    }
    const int nw = (nbins + 31) >> 5;
    if (lane == 0 && wid < nw) scanb[wid] = s;
    __syncthreads();
    if (t < 32) {
        uint32_t w = (t < nw) ? scanb[t] : 0u;
        uint32_t ws = w;
        #pragma unroll
        for (int off = 1; off < 32; off <<= 1) {
            uint32_t u = __shfl_down_sync(0xFFFFFFFFu, ws, off);
            if (t + off < 32) ws += u;
        }
        if (t < nw) scanb[t] = ws - w;   // exclusive suffix over warps above
    }
    __syncthreads();
    if (t < nbins) {
        uint32_t above = (s - v) + scanb[wid];
        if (above < Kre && above + v >= Kre) {
            sel[0] = (uint32_t)t; sel[1] = above; sel[2] = v;
        }
    }
    __syncthreads();
}

__global__ __launch_bounds__(NT, 3)
void topk_relu_kernel(const float* __restrict__ x, float* __restrict__ out) {
    extern __shared__ uint32_t smem[];
    uint32_t* hist  = smem;              // [256]
    uint32_t* scanb = hist + 256;        // [32]
    uint32_t* sel   = scanb + 32;        // [4]
    uint32_t* cnt   = sel + 4;           // [0]=cand, [1]=eq, [2]=npos
    uint32_t* wred  = cnt + 4;           // [NW]
    uint32_t* ck    = wred + NW;         // [CAND_MAX] candidate keys
    uint32_t* ci    = ck + CAND_MAX;     // [CAND_MAX] candidate indices
    uint32_t* eqi   = ci + CAND_MAX;     // [MAX_EQ]

    const int row  = blockIdx.x;
    const int t    = threadIdx.x;
    const int lane = t & 31;
    const int wid  = t >> 5;
    const float4* __restrict__ xv =
        reinterpret_cast<const float4*>(x + (size_t)row * NCOLS);
    float* __restrict__ orow = out + (size_t)row * NCOLS;
    float4* __restrict__ ov = reinterpret_cast<float4*>(orow);

    if (t == 0) { cnt[0] = 0; cnt[1] = 0; }
    __syncthreads();

    // ---- fused main pass: 6 front-batched loads, 6 zero-stores, collect ----
    const float4 z4 = make_float4(0.f, 0.f, 0.f, 0.f);
    #pragma unroll
    for (int it = 0; it < VEC_IT; it += BATCH) {
        const float4* xp = xv + it * NT + t;   // batch offsets are immediates
        float4* op = ov + it * NT + t;
        float4 v[BATCH];
        #pragma unroll
        for (int b = 0; b < BATCH; b++)
            v[b] = __ldcs(xp + b * NT);
        #pragma unroll
        for (int b = 0; b < BATCH; b++)
            __stcs(op + b * NT, z4);
        #pragma unroll
        for (int b = 0; b < BATCH; b++) {
            float m = fmaxf(fmaxf(v[b].x, v[b].y), fmaxf(v[b].z, v[b].w));
            if (m > TCAND) collect4(v[b], ((it + b) * NT + t) * 4, cnt, ck, ci);
        }
    }
    __syncthreads();

    const uint32_t ncand = cnt[0];

    // ---- fast path A: rank epilogue (one thread per candidate) ----
    if (ncand >= KSEL && ncand <= (uint32_t)NT) {
        if (t < (int)ncand) {
            uint32_t myk = ck[t], myi = ci[t];
            uint32_t r = 0;
            for (uint32_t j = 0; j < ncand; j++) {
                uint32_t kj = ck[j];
                uint32_t ij = ci[j];
                r += (kj > myk) || (kj == myk && ij < myi);
            }
            if (r < KSEL) orow[myi] = relu_of_key(myk);
        }
        return;
    }

    uint32_t Pc, Rr, nc;
    int shc;
    if (ncand > (uint32_t)NT && ncand <= CAND_MAX) {
        // ---- fast path B: larger candidate set -> radix select ----
        Pc = 0; shc = 32; Rr = KSEL; nc = ncand;
    } else {
        // ---- rare paths: need the positive count (L2-resident re-read) ----
        uint32_t c0 = 0;
        #pragma unroll 4
        for (int it = 0; it < VEC_IT; it++) {
            float4 v = __ldcs(xv + it * NT + t);
            c0 += (v.x > 0.0f) + (v.y > 0.0f) + (v.z > 0.0f) + (v.w > 0.0f);
        }
        #pragma unroll
        for (int off = 16; off > 0; off >>= 1)
            c0 += __shfl_down_sync(0xFFFFFFFFu, c0, off);
        if (lane == 0) wred[wid] = c0;
        __syncthreads();
        if (t == 0) {
            uint32_t s = 0;
            #pragma unroll
            for (int w = 0; w < NW; w++) s += wred[w];
            cnt[2] = s;
        }
        __syncthreads();
        const uint32_t npos = cnt[2];

        if (npos < KSEL) {
            // 64th largest <= 0: output is exactly relu(x)
            #pragma unroll 4
            for (int it = 0; it < VEC_IT; it++) {
                int vi = it * NT + t;
                float4 v = __ldcs(xv + vi);
                v.x = fmaxf(v.x, 0.0f); v.y = fmaxf(v.y, 0.0f);
                v.z = fmaxf(v.z, 0.0f); v.w = fmaxf(v.w, 0.0f);
                __stcs(ov + vi, v);
            }
            return;
        }

        // generic fallback: key-space radix refine (any distribution)
        const uint32_t* xb = reinterpret_cast<const uint32_t*>(x) + (size_t)row * NCOLS;
        uint32_t P = 0, R = KSEL, bc = NCOLS;
        int sh = 32;
        while (bc > CAND_MAX && sh > 0) {
            int nsh = (sh >= 8) ? sh - 8 : 0;
            int nb  = 1 << (sh - nsh);
            for (int i = t; i < nb; i += NT) hist[i] = 0;
            __syncthreads();
            for (int i = t; i < NCOLS; i += NT) {
                uint32_t k = key_of(xb[i]);
                if (sh == 32 || (k >> sh) == P)
                    atomicAdd(&hist[(k >> nsh) & (nb - 1)], 1u);
            }
            __syncthreads();
            uint32_t hv = (t < nb) ? hist[t] : 0u;
            suffix_select(hv, scanb, sel, nb, R, t, lane, wid);
            P  = ((sh == 32) ? 0u : (P << (sh - nsh))) | sel[0];
            R -= sel[1];
            bc = sel[2];
            sh = nsh;
            __syncthreads();
        }
        const uint32_t kLo = (sh == 32) ? 0u : (P << sh);
        const uint32_t kHi = (sh == 32) ? 0xFFFFFFFFu
                             : (uint32_t)(((((uint64_t)P) + 1ull) << sh) - 1ull);
        if (t == 0) cnt[0] = 0;
        __syncthreads();
        for (int i = t; i < NCOLS; i += NT) {
            uint32_t k = key_of(xb[i]);
            if (k > kHi) {
                orow[i] = relu_of_key(k);       // definitely top-64
            } else if (k >= kLo) {
                uint32_t p = atomicAdd(&cnt[0], 1u);
                if (p < CAND_MAX) { ck[p] = k; ci[p] = (uint32_t)i; }
            }
        }
        __syncthreads();
        nc = cnt[0]; if (nc > CAND_MAX) nc = CAND_MAX;
        Pc = P; shc = sh; Rr = R;
    }

    // ---- exact threshold: 8-bit radix select over candidates ----
    while (shc > 0) {
        int nsh = (shc >= 8) ? shc - 8 : 0;
        int nb  = 1 << (shc - nsh);
        for (int i = t; i < nb; i += NT) hist[i] = 0;
        __syncthreads();
        for (uint32_t i = t; i < nc; i += NT) {
            uint32_t k = ck[i];
            if (shc == 32 || (k >> shc) == Pc)
                atomicAdd(&hist[(k >> nsh) & (nb - 1)], 1u);
        }
        __syncthreads();
        uint32_t hv = (t < nb) ? hist[t] : 0u;
        suffix_select(hv, scanb, sel, nb, Rr, t, lane, wid);
        Pc  = ((shc == 32) ? 0u : (Pc << (shc - nsh))) | sel[0];
        Rr -= sel[1];
        shc = nsh;
        __syncthreads();
    }
    const uint32_t Tkey   = Pc;
    const uint32_t keepEq = Rr;                 // # threshold-equal keys to keep
    const float    tval   = relu_of_key(Tkey);

    // ---- scatter strictly-above candidates; collect exact ties ----
    for (uint32_t i = t; i < nc; i += NT) {
        uint32_t k = ck[i];
        if (k > Tkey) {
            orow[ci[i]] = relu_of_key(k);
        } else if (k == Tkey) {
            uint32_t p = atomicAdd(&cnt[1], 1u);
            if (p < MAX_EQ) eqi[p] = ci[i];
        }
    }
    __syncthreads();

    // ---- ties: keep the keepEq equal-keys with smallest indices ----
    uint32_t ne = cnt[1];
    if (ne > MAX_EQ) ne = MAX_EQ;
    if (ne <= keepEq) {
        for (uint32_t e = t; e < ne; e += NT) orow[eqi[e]] = tval;
    } else {
        for (uint32_t e = t; e < ne; e += NT) {
            uint32_t idx = eqi[e];
            uint32_t c = 0;
            for (uint32_t j = 0; j < ne; j++) c += (eqi[j] < idx);
            if (c < keepEq) orow[idx] = tval;
        }
    }
}

extern "C" void kernel_launch(void* const* d_in, const int* in_sizes, int n_in,
                              void* d_out, int out_size) {
    const float* x = (const float*)d_in[0];
    float* out = (float*)d_out;
    const int rows = in_sizes[0] / NCOLS;

    cudaFuncSetAttribute(topk_relu_kernel,
                         cudaFuncAttributeMaxDynamicSharedMemorySize, SMEM_BYTES);
    topk_relu_kernel<<<rows, NT, SMEM_BYTES>>>(x, out);
}